// round 1
// baseline (speedup 1.0000x reference)
#include <cuda_runtime.h>
#include <math.h>

#define N_NODES 10000
#define N_EDGES 320000

// ---------------- scratch (static device allocations) ----------------
__device__ float g_C1[N_NODES * 512];   // x @ (W1a_top - W1a_bot)
__device__ float g_D1[N_NODES * 512];   // x @ W1a_bot
__device__ float g_H1[N_NODES * 256];   // layer-1 aggregated node features
__device__ float g_C2[N_NODES * 256];   // H1 @ (W1b_top - W1b_bot)
__device__ float g_D2[N_NODES * 256];   // H1 @ W1b_bot
__device__ float g_H2[N_NODES * 128];   // layer-2 aggregated node features
__device__ int   g_hist[N_NODES + 1];
__device__ int   g_cursor[N_NODES];
__device__ int   g_src_s[N_EDGES];      // edges sorted by dst
__device__ int   g_dst_s[N_EDGES];

// ---------------- init ----------------
__global__ void k_zero() {
    int stride = gridDim.x * blockDim.x;
    int i0 = blockIdx.x * blockDim.x + threadIdx.x;
    for (int j = i0; j < N_NODES * 256; j += stride) g_H1[j] = 0.f;
    for (int j = i0; j < N_NODES * 128; j += stride) g_H2[j] = 0.f;
    for (int j = i0; j <= N_NODES;      j += stride) g_hist[j] = 0;
    for (int j = i0; j < N_NODES;       j += stride) g_cursor[j] = 0;
}

// ---------------- counting sort by dst ----------------
__global__ void k_hist(const int* __restrict__ dst) {
    int e = blockIdx.x * blockDim.x + threadIdx.x;
    if (e < N_EDGES) atomicAdd(&g_hist[dst[e] + 1], 1);
}

__global__ void k_scan() {
    __shared__ int s[1024];
    __shared__ int carry;
    int tid = threadIdx.x;
    if (tid == 0) carry = 0;
    __syncthreads();
    for (int base = 0; base < N_NODES + 1; base += 1024) {
        int i = base + tid;
        int v = (i < N_NODES + 1) ? g_hist[i] : 0;
        s[tid] = v;
        __syncthreads();
        for (int off = 1; off < 1024; off <<= 1) {
            int t = (tid >= off) ? s[tid - off] : 0;
            __syncthreads();
            s[tid] += t;
            __syncthreads();
        }
        int out = s[tid] + carry;
        if (i < N_NODES + 1) g_hist[i] = out;
        __syncthreads();
        if (tid == 1023) carry = out;
        __syncthreads();
    }
}

__global__ void k_scatter(const int* __restrict__ src, const int* __restrict__ dst) {
    int e = blockIdx.x * blockDim.x + threadIdx.x;
    if (e < N_EDGES) {
        int d = dst[e];
        int pos = g_hist[d] + atomicAdd(&g_cursor[d], 1);
        g_src_s[pos] = src[e];
        g_dst_s[pos] = d;
    }
}

// ---------------- node dual GEMM: C = X@(Wtop-Wbot), D = X@Wbot ----------------
// X: [N_NODES, K], W: [2K, N] row-major. BM=64, BN=64, BK=16, 256 threads, 4x4 micro.
template <int K, int N>
__launch_bounds__(256)
__global__ void k_node_dual(const float* __restrict__ X, const float* __restrict__ W,
                            float* __restrict__ C, float* __restrict__ D) {
    __shared__ float As[16][68];
    __shared__ float Bd[16][64];
    __shared__ float Bb[16][64];
    int tid = threadIdx.x;
    int tx = tid & 15, ty = tid >> 4;
    int m0 = blockIdx.x * 64;
    int n0 = blockIdx.y * 64;

    float accC[4][4] = {};
    float accD[4][4] = {};

    for (int k0 = 0; k0 < K; k0 += 16) {
        {   // A tile: 64 x 16, one float4 per thread
            int m = tid >> 2;
            int kq = (tid & 3) * 4;
            int gm = m0 + m;
            float4 a = make_float4(0.f, 0.f, 0.f, 0.f);
            if (gm < N_NODES) a = *(const float4*)&X[gm * K + k0 + kq];
            As[kq + 0][m] = a.x; As[kq + 1][m] = a.y;
            As[kq + 2][m] = a.z; As[kq + 3][m] = a.w;
        }
        {   // B tiles: 16 x 64 (top & bot)
            int k  = tid >> 4;
            int nq = (tid & 15) * 4;
            float4 t = *(const float4*)&W[(k0 + k) * N + n0 + nq];
            float4 b = *(const float4*)&W[(K + k0 + k) * N + n0 + nq];
            *(float4*)&Bb[k][nq] = b;
            float4 dv = make_float4(t.x - b.x, t.y - b.y, t.z - b.z, t.w - b.w);
            *(float4*)&Bd[k][nq] = dv;
        }
        __syncthreads();
#pragma unroll
        for (int kk = 0; kk < 16; kk++) {
            float a[4];
#pragma unroll
            for (int i = 0; i < 4; i++) a[i] = As[kk][ty * 4 + i];
            float4 vd = *(float4*)&Bd[kk][tx * 4];
            float4 vb = *(float4*)&Bb[kk][tx * 4];
            float bd[4] = {vd.x, vd.y, vd.z, vd.w};
            float bb[4] = {vb.x, vb.y, vb.z, vb.w};
#pragma unroll
            for (int i = 0; i < 4; i++)
#pragma unroll
                for (int j = 0; j < 4; j++) {
                    accC[i][j] += a[i] * bd[j];
                    accD[i][j] += a[i] * bb[j];
                }
        }
        __syncthreads();
    }
#pragma unroll
    for (int i = 0; i < 4; i++) {
        int gm = m0 + ty * 4 + i;
        if (gm < N_NODES) {
            float4 c = make_float4(accC[i][0], accC[i][1], accC[i][2], accC[i][3]);
            float4 d = make_float4(accD[i][0], accD[i][1], accD[i][2], accD[i][3]);
            *(float4*)&C[gm * N + n0 + tx * 4] = c;
            *(float4*)&D[gm * N + n0 + tx * 4] = d;
        }
    }
}

// ---------------- fused per-edge GEMM + segmented max ----------------
// z[e,:] = relu(C[dst_e] + D[src_e] + b1);  out = relu(z @ W2 + b2);  AGG[d] = max over edges
// BM=128 edges, BN=128 cols, BK=16, 256 threads, 8x8 micro. Edges sorted by dst.
template <int K, int NOUT>
__launch_bounds__(256)
__global__ void k_edge_gemm(const float* __restrict__ C, const float* __restrict__ D,
                            const float* __restrict__ b1, const float* __restrict__ W2,
                            const float* __restrict__ b2, float* __restrict__ AGG) {
    __shared__ float As[16][129];
    __shared__ float Bs[16][128];
    __shared__ int sdst[128];
    __shared__ int ssrc[128];

    int tid = threadIdx.x;
    int tx = tid & 15, ty = tid >> 4;
    int e0 = blockIdx.x * 128;
    int n0 = blockIdx.y * 128;

    if (tid < 128) {
        sdst[tid] = g_dst_s[e0 + tid];
        ssrc[tid] = g_src_s[e0 + tid];
    }
    __syncthreads();

    int m  = tid >> 1;
    int kq = (tid & 1) * 8;
    int rowC = sdst[m] * K;
    int rowS = ssrc[m] * K;

    float acc[8][8] = {};

    for (int k0 = 0; k0 < K; k0 += 16) {
        {   // gathered A tile with fused bias+relu
            float4 c0 = *(const float4*)&C[rowC + k0 + kq];
            float4 c1 = *(const float4*)&C[rowC + k0 + kq + 4];
            float4 d0 = *(const float4*)&D[rowS + k0 + kq];
            float4 d1 = *(const float4*)&D[rowS + k0 + kq + 4];
            float4 e0v = *(const float4*)&b1[k0 + kq];
            float4 e1v = *(const float4*)&b1[k0 + kq + 4];
            As[kq + 0][m] = fmaxf(c0.x + d0.x + e0v.x, 0.f);
            As[kq + 1][m] = fmaxf(c0.y + d0.y + e0v.y, 0.f);
            As[kq + 2][m] = fmaxf(c0.z + d0.z + e0v.z, 0.f);
            As[kq + 3][m] = fmaxf(c0.w + d0.w + e0v.w, 0.f);
            As[kq + 4][m] = fmaxf(c1.x + d1.x + e1v.x, 0.f);
            As[kq + 5][m] = fmaxf(c1.y + d1.y + e1v.y, 0.f);
            As[kq + 6][m] = fmaxf(c1.z + d1.z + e1v.z, 0.f);
            As[kq + 7][m] = fmaxf(c1.w + d1.w + e1v.w, 0.f);
        }
        {   // B tile 16 x 128
            int k  = tid >> 4;
            int nq = (tid & 15) * 8;
            *(float4*)&Bs[k][nq]     = *(const float4*)&W2[(k0 + k) * NOUT + n0 + nq];
            *(float4*)&Bs[k][nq + 4] = *(const float4*)&W2[(k0 + k) * NOUT + n0 + nq + 4];
        }
        __syncthreads();
#pragma unroll
        for (int kk = 0; kk < 16; kk++) {
            float a[8];
#pragma unroll
            for (int i = 0; i < 8; i++) a[i] = As[kk][ty * 8 + i];
            float4 v0 = *(float4*)&Bs[kk][tx * 8];
            float4 v1 = *(float4*)&Bs[kk][tx * 8 + 4];
            float b[8] = {v0.x, v0.y, v0.z, v0.w, v1.x, v1.y, v1.z, v1.w};
#pragma unroll
            for (int i = 0; i < 8; i++)
#pragma unroll
                for (int j = 0; j < 8; j++)
                    acc[i][j] += a[i] * b[j];
        }
        __syncthreads();
    }

    // epilogue: bias + relu + register-level segmented max (edges sorted by dst)
    float4 w0 = *(const float4*)&b2[n0 + tx * 8];
    float4 w1 = *(const float4*)&b2[n0 + tx * 8 + 4];
    float bias[8] = {w0.x, w0.y, w0.z, w0.w, w1.x, w1.y, w1.z, w1.w};
    int dloc[8];
#pragma unroll
    for (int i = 0; i < 8; i++) dloc[i] = sdst[ty * 8 + i];

#pragma unroll
    for (int j = 0; j < 8; j++) {
        int col = n0 + tx * 8 + j;
        float mx = fmaxf(acc[0][j] + bias[j], 0.f);
#pragma unroll
        for (int i = 1; i < 8; i++) {
            float v = fmaxf(acc[i][j] + bias[j], 0.f);
            if (dloc[i] == dloc[i - 1]) {
                mx = fmaxf(mx, v);
            } else {
                atomicMax((int*)&AGG[dloc[i - 1] * NOUT + col], __float_as_int(mx));
                mx = v;
            }
        }
        atomicMax((int*)&AGG[dloc[7] * NOUT + col], __float_as_int(mx));
    }
}

// ---------------- dense head: relu(H2@W3+b3) -> sigmoid(@W4+b4) ----------------
__global__ void k_head(const float* __restrict__ W3, const float* __restrict__ b3,
                       const float* __restrict__ W4, const float* __restrict__ b4,
                       float* __restrict__ out) {
    __shared__ float sh[128];
    __shared__ float red[2];
    int n = blockIdx.x;
    int t = threadIdx.x;   // 64 threads
    sh[t]      = g_H2[n * 128 + t];
    sh[t + 64] = g_H2[n * 128 + 64 + t];
    __syncthreads();
    float s = b3[t];
#pragma unroll 8
    for (int k = 0; k < 128; k++) s += sh[k] * W3[k * 64 + t];
    s = fmaxf(s, 0.f);
    float p = s * W4[t];
#pragma unroll
    for (int off = 16; off > 0; off >>= 1) p += __shfl_down_sync(0xffffffffu, p, off);
    if ((t & 31) == 0) red[t >> 5] = p;
    __syncthreads();
    if (t == 0) {
        float z = red[0] + red[1] + b4[0];
        out[n] = 1.f / (1.f + expf(-z));
    }
}

// ---------------- launch ----------------
extern "C" void kernel_launch(void* const* d_in, const int* in_sizes, int n_in,
                              void* d_out, int out_size) {
    const float* x   = (const float*)d_in[0];
    const int*   ei  = (const int*)d_in[1];
    const int*   src = ei;
    const int*   dst = ei + N_EDGES;
    const float* W1a = (const float*)d_in[2];
    const float* b1a = (const float*)d_in[3];
    const float* W2a = (const float*)d_in[4];
    const float* b2a = (const float*)d_in[5];
    const float* W1b = (const float*)d_in[6];
    const float* b1b = (const float*)d_in[7];
    const float* W2b = (const float*)d_in[8];
    const float* b2b = (const float*)d_in[9];
    const float* W3  = (const float*)d_in[10];
    const float* b3  = (const float*)d_in[11];
    const float* W4  = (const float*)d_in[12];
    const float* b4  = (const float*)d_in[13];
    float* out = (float*)d_out;

    void *pC1, *pD1, *pH1, *pC2, *pD2, *pH2;
    cudaGetSymbolAddress(&pC1, g_C1);
    cudaGetSymbolAddress(&pD1, g_D1);
    cudaGetSymbolAddress(&pH1, g_H1);
    cudaGetSymbolAddress(&pC2, g_C2);
    cudaGetSymbolAddress(&pD2, g_D2);
    cudaGetSymbolAddress(&pH2, g_H2);

    // init + counting sort of edges by dst
    k_zero<<<512, 256>>>();
    k_hist<<<(N_EDGES + 255) / 256, 256>>>(dst);
    k_scan<<<1, 1024>>>();
    k_scatter<<<(N_EDGES + 255) / 256, 256>>>(src, dst);

    // layer 1: node-level precompute, then fused per-edge GEMM + max-agg
    {
        dim3 g((N_NODES + 63) / 64, 512 / 64);
        k_node_dual<128, 512><<<g, 256>>>(x, W1a, (float*)pC1, (float*)pD1);
    }
    {
        dim3 g(N_EDGES / 128, 256 / 128);
        k_edge_gemm<512, 256><<<g, 256>>>((const float*)pC1, (const float*)pD1,
                                          b1a, W2a, b2a, (float*)pH1);
    }

    // layer 2
    {
        dim3 g((N_NODES + 63) / 64, 256 / 64);
        k_node_dual<256, 256><<<g, 256>>>((const float*)pH1, W1b, (float*)pC2, (float*)pD2);
    }
    {
        dim3 g(N_EDGES / 128, 128 / 128);
        k_edge_gemm<256, 128><<<g, 256>>>((const float*)pC2, (const float*)pD2,
                                          b1b, W2b, b2b, (float*)pH2);
    }

    // head
    k_head<<<N_NODES, 64>>>(W3, b3, W4, b4, out);
}

// round 5
// speedup vs baseline: 1.6300x; 1.6300x over previous
#include <cuda_runtime.h>
#include <cuda_bf16.h>
#include <stdint.h>
#include <math.h>

#define N_NODES 10000
#define N_EDGES 320000

// ---------------- scratch (static device allocations) ----------------
__device__ float g_C1[N_NODES * 512];
__device__ float g_D1[N_NODES * 512];
__device__ float g_H1[N_NODES * 256];
__device__ float g_C2[N_NODES * 256];
__device__ float g_D2[N_NODES * 256];
__device__ float g_H2[N_NODES * 128];
__device__ int   g_hist[N_NODES + 1];
__device__ int   g_cursor[N_NODES];
__device__ int   g_src_s[N_EDGES];
__device__ int   g_dst_s[N_EDGES];
// pre-split transposed weights (K-major [NOUT, K]) bf16 hi/lo
__device__ __nv_bfloat16 g_WH1[256 * 512];
__device__ __nv_bfloat16 g_WL1[256 * 512];
__device__ __nv_bfloat16 g_WH2[128 * 256];
__device__ __nv_bfloat16 g_WL2[128 * 256];

// ---------------- helpers ----------------
__device__ __forceinline__ void mma_bf16(float* c,
    uint32_t a0, uint32_t a1, uint32_t a2, uint32_t a3,
    uint32_t b0, uint32_t b1) {
    asm volatile(
        "mma.sync.aligned.m16n8k16.row.col.f32.bf16.bf16.f32 "
        "{%0,%1,%2,%3}, {%4,%5,%6,%7}, {%8,%9}, {%0,%1,%2,%3};"
        : "+f"(c[0]), "+f"(c[1]), "+f"(c[2]), "+f"(c[3])
        : "r"(a0), "r"(a1), "r"(a2), "r"(a3), "r"(b0), "r"(b1));
}

__device__ __forceinline__ void split2(float a, float b, uint32_t& h, uint32_t& l) {
    __nv_bfloat16 ha = __float2bfloat16(a), hb = __float2bfloat16(b);
    float ra = a - __bfloat162float(ha);
    float rb = b - __bfloat162float(hb);
    __nv_bfloat162 hp; hp.x = ha; hp.y = hb;
    __nv_bfloat162 lp; lp.x = __float2bfloat16(ra); lp.y = __float2bfloat16(rb);
    h = *reinterpret_cast<uint32_t*>(&hp);
    l = *reinterpret_cast<uint32_t*>(&lp);
}

// ---------------- init ----------------
__global__ void k_zero() {
    int stride = gridDim.x * blockDim.x;
    int i0 = blockIdx.x * blockDim.x + threadIdx.x;
    for (int j = i0; j < N_NODES * 256; j += stride) g_H1[j] = 0.f;
    for (int j = i0; j < N_NODES * 128; j += stride) g_H2[j] = 0.f;
    for (int j = i0; j <= N_NODES;      j += stride) g_hist[j] = 0;
    for (int j = i0; j < N_NODES;       j += stride) g_cursor[j] = 0;
}

// ---------------- counting sort by dst ----------------
__global__ void k_hist(const int* __restrict__ dst) {
    int e = blockIdx.x * blockDim.x + threadIdx.x;
    if (e < N_EDGES) atomicAdd(&g_hist[dst[e] + 1], 1);
}
__global__ void k_scan() {
    __shared__ int s[1024];
    __shared__ int carry;
    int tid = threadIdx.x;
    if (tid == 0) carry = 0;
    __syncthreads();
    for (int base = 0; base < N_NODES + 1; base += 1024) {
        int i = base + tid;
        int v = (i < N_NODES + 1) ? g_hist[i] : 0;
        s[tid] = v;
        __syncthreads();
        for (int off = 1; off < 1024; off <<= 1) {
            int t = (tid >= off) ? s[tid - off] : 0;
            __syncthreads();
            s[tid] += t;
            __syncthreads();
        }
        int out = s[tid] + carry;
        if (i < N_NODES + 1) g_hist[i] = out;
        __syncthreads();
        if (tid == 1023) carry = out;
        __syncthreads();
    }
}
__global__ void k_scatter(const int* __restrict__ src, const int* __restrict__ dst) {
    int e = blockIdx.x * blockDim.x + threadIdx.x;
    if (e < N_EDGES) {
        int d = dst[e];
        int pos = g_hist[d] + atomicAdd(&g_cursor[d], 1);
        g_src_s[pos] = src[e];
        g_dst_s[pos] = d;
    }
}

// ---------------- weight prep: W2 [K,NOUT] fp32 -> W2^T [NOUT,K] bf16 hi/lo ----------------
template <int KW, int NOUT>
__global__ void k_prep(const float* __restrict__ W2,
                       __nv_bfloat16* __restrict__ WH, __nv_bfloat16* __restrict__ WL) {
    int i = blockIdx.x * blockDim.x + threadIdx.x;
    if (i < KW * NOUT) {
        int n = i / KW, k = i % KW;
        float w = W2[k * NOUT + n];
        __nv_bfloat16 h = __float2bfloat16(w);
        WH[i] = h;
        WL[i] = __float2bfloat16(w - __bfloat162float(h));
    }
}

// ---------------- node dual GEMM: C = X@(Wtop-Wbot), D = X@Wbot ----------------
template <int K, int N>
__launch_bounds__(256)
__global__ void k_node_dual(const float* __restrict__ X, const float* __restrict__ W,
                            float* __restrict__ C, float* __restrict__ D) {
    __shared__ float As[16][68];
    __shared__ float Bd[16][64];
    __shared__ float Bb[16][64];
    int tid = threadIdx.x;
    int tx = tid & 15, ty = tid >> 4;
    int m0 = blockIdx.x * 64;
    int n0 = blockIdx.y * 64;
    float accC[4][4] = {};
    float accD[4][4] = {};
    for (int k0 = 0; k0 < K; k0 += 16) {
        {
            int m = tid >> 2;
            int kq = (tid & 3) * 4;
            int gm = m0 + m;
            float4 a = make_float4(0.f, 0.f, 0.f, 0.f);
            if (gm < N_NODES) a = *(const float4*)&X[gm * K + k0 + kq];
            As[kq + 0][m] = a.x; As[kq + 1][m] = a.y;
            As[kq + 2][m] = a.z; As[kq + 3][m] = a.w;
        }
        {
            int k  = tid >> 4;
            int nq = (tid & 15) * 4;
            float4 t = *(const float4*)&W[(k0 + k) * N + n0 + nq];
            float4 b = *(const float4*)&W[(K + k0 + k) * N + n0 + nq];
            *(float4*)&Bb[k][nq] = b;
            float4 dv = make_float4(t.x - b.x, t.y - b.y, t.z - b.z, t.w - b.w);
            *(float4*)&Bd[k][nq] = dv;
        }
        __syncthreads();
#pragma unroll
        for (int kk = 0; kk < 16; kk++) {
            float a[4];
#pragma unroll
            for (int i = 0; i < 4; i++) a[i] = As[kk][ty * 4 + i];
            float4 vd = *(float4*)&Bd[kk][tx * 4];
            float4 vb = *(float4*)&Bb[kk][tx * 4];
            float bd[4] = {vd.x, vd.y, vd.z, vd.w};
            float bb[4] = {vb.x, vb.y, vb.z, vb.w};
#pragma unroll
            for (int i = 0; i < 4; i++)
#pragma unroll
                for (int j = 0; j < 4; j++) {
                    accC[i][j] += a[i] * bd[j];
                    accD[i][j] += a[i] * bb[j];
                }
        }
        __syncthreads();
    }
#pragma unroll
    for (int i = 0; i < 4; i++) {
        int gm = m0 + ty * 4 + i;
        if (gm < N_NODES) {
            float4 c = make_float4(accC[i][0], accC[i][1], accC[i][2], accC[i][3]);
            float4 d = make_float4(accD[i][0], accD[i][1], accD[i][2], accD[i][3]);
            *(float4*)&C[gm * N + n0 + tx * 4] = c;
            *(float4*)&D[gm * N + n0 + tx * 4] = d;
        }
    }
}

// ---------------- mma.sync edge GEMM + segmented max ----------------
// Block: 256 thr (8 warps: 4 M x 2 N). Tile: 128 edges x 128 cols. K chunk 32.
// A = relu(C[dst]+D[src]+b1) split bf16 hi/lo in SMEM; B = pre-split W2^T hi/lo.
// acc += Ah*Bh + Ah*Bl + Al*Bh  (fp32).
// SMEM layout (bytes): sdst@0[512], ssrc@512[512], data@1024:
//   Ah@1024, Al@11264, Bh@21504, Bl@31744 (each 128 rows x 80B)
//   stage (epilogue, reuses data region): @1024, 128 x 66 floats
#define SM_SDST 0
#define SM_SSRC 512
#define SM_AH   1024
#define SM_AL   11264
#define SM_BH   21504
#define SM_BL   31744
#define SM_STG  1024
#define EDGE_SMEM 41984

template <int KW, int NOUT>
__global__ void __launch_bounds__(256, 2) k_edge_mma(
    const float* __restrict__ C, const float* __restrict__ D, const float* __restrict__ b1v,
    const __nv_bfloat16* __restrict__ WH, const __nv_bfloat16* __restrict__ WL,
    const float* __restrict__ b2, float* __restrict__ AGG)
{
    extern __shared__ char smem[];
    const int tid = threadIdx.x;
    const int wid = tid >> 5, lid = tid & 31;
    const int warp_m = wid & 3, warp_n = wid >> 2;
    const int gid = lid >> 2, tig = lid & 3;

    int* sdst = (int*)(smem + SM_SDST);
    int* ssrc = (int*)(smem + SM_SSRC);

    const int e0 = blockIdx.x * 128;
    const int n0 = blockIdx.y * 128;
    if (tid < 128) {
        sdst[tid] = g_dst_s[e0 + tid];
        ssrc[tid] = g_src_s[e0 + tid];
    }
    __syncthreads();

    // per-thread fill assignments
    const int fm = tid >> 1;            // row (edge or weight row) 0..127
    const int fk = (tid & 1) * 16;      // k-offset within 32-chunk
    const size_t rowC = (size_t)sdst[fm] * KW;
    const size_t rowD = (size_t)ssrc[fm] * KW;
    const size_t rowW = (size_t)(n0 + fm) * KW;

    float acc[2][8][4];
#pragma unroll
    for (int a = 0; a < 2; ++a)
#pragma unroll
        for (int b = 0; b < 8; ++b)
#pragma unroll
            for (int c = 0; c < 4; ++c) acc[a][b][c] = 0.f;

    constexpr int NCH = KW / 32;
    for (int ch = 0; ch < NCH; ++ch) {
        const int k0 = ch * 32 + fk;
        // ---- A tile: fused gather + bias + relu + hi/lo split (16 k per thread)
        {
            const float* cp = C + rowC + k0;
            const float* dp = D + rowD + k0;
            const float* bp = b1v + k0;
            uint32_t h[8], l[8];
#pragma unroll
            for (int g = 0; g < 4; ++g) {
                float4 cv = *(const float4*)(cp + g * 4);
                float4 dv = *(const float4*)(dp + g * 4);
                float4 bv = *(const float4*)(bp + g * 4);
                float v0 = fmaxf(cv.x + dv.x + bv.x, 0.f);
                float v1 = fmaxf(cv.y + dv.y + bv.y, 0.f);
                float v2 = fmaxf(cv.z + dv.z + bv.z, 0.f);
                float v3 = fmaxf(cv.w + dv.w + bv.w, 0.f);
                split2(v0, v1, h[g * 2], l[g * 2]);
                split2(v2, v3, h[g * 2 + 1], l[g * 2 + 1]);
            }
            char* pa = smem + SM_AH + fm * 80 + fk * 2;
            char* pl = smem + SM_AL + fm * 80 + fk * 2;
            *(uint4*)pa       = make_uint4(h[0], h[1], h[2], h[3]);
            *(uint4*)(pa + 16) = make_uint4(h[4], h[5], h[6], h[7]);
            *(uint4*)pl       = make_uint4(l[0], l[1], l[2], l[3]);
            *(uint4*)(pl + 16) = make_uint4(l[4], l[5], l[6], l[7]);
        }
        // ---- B tile: pre-split weights, 16 bf16 per thread per buffer
        {
            const uint4* wh = (const uint4*)(WH + rowW + k0);
            const uint4* wl = (const uint4*)(WL + rowW + k0);
            char* pb = smem + SM_BH + fm * 80 + fk * 2;
            char* pl = smem + SM_BL + fm * 80 + fk * 2;
            *(uint4*)pb        = wh[0];
            *(uint4*)(pb + 16) = wh[1];
            *(uint4*)pl        = wl[0];
            *(uint4*)(pl + 16) = wl[1];
        }
        __syncthreads();

        // ---- 2 k-steps of 16
#pragma unroll
        for (int ks = 0; ks < 2; ++ks) {
            const int kc = ks * 16 + tig * 2;
            uint32_t ah[2][4], al[2][4];
#pragma unroll
            for (int mt = 0; mt < 2; ++mt) {
                int r = warp_m * 32 + mt * 16 + gid;
                const char* baseH = smem + SM_AH + r * 80;
                const char* baseL = smem + SM_AL + r * 80;
                ah[mt][0] = *(const uint32_t*)(baseH + kc * 2);
                ah[mt][1] = *(const uint32_t*)(baseH + 8 * 80 + kc * 2);
                ah[mt][2] = *(const uint32_t*)(baseH + (kc + 8) * 2);
                ah[mt][3] = *(const uint32_t*)(baseH + 8 * 80 + (kc + 8) * 2);
                al[mt][0] = *(const uint32_t*)(baseL + kc * 2);
                al[mt][1] = *(const uint32_t*)(baseL + 8 * 80 + kc * 2);
                al[mt][2] = *(const uint32_t*)(baseL + (kc + 8) * 2);
                al[mt][3] = *(const uint32_t*)(baseL + 8 * 80 + (kc + 8) * 2);
            }
#pragma unroll
            for (int j = 0; j < 8; ++j) {
                int n = warp_n * 64 + j * 8 + gid;
                const char* bH = smem + SM_BH + n * 80;
                const char* bL = smem + SM_BL + n * 80;
                uint32_t bh0 = *(const uint32_t*)(bH + kc * 2);
                uint32_t bh1 = *(const uint32_t*)(bH + (kc + 8) * 2);
                uint32_t bl0 = *(const uint32_t*)(bL + kc * 2);
                uint32_t bl1 = *(const uint32_t*)(bL + (kc + 8) * 2);
#pragma unroll
                for (int mt = 0; mt < 2; ++mt) {
                    mma_bf16(acc[mt][j], ah[mt][0], ah[mt][1], ah[mt][2], ah[mt][3], bh0, bh1);
                    mma_bf16(acc[mt][j], ah[mt][0], ah[mt][1], ah[mt][2], ah[mt][3], bl0, bl1);
                    mma_bf16(acc[mt][j], al[mt][0], al[mt][1], al[mt][2], al[mt][3], bh0, bh1);
                }
            }
        }
        __syncthreads();
    }

    // ---- epilogue: stage to SMEM, bias+relu, segmented max over sorted dst
    float* stage = (float*)(smem + SM_STG);
#pragma unroll 1
    for (int p = 0; p < 2; ++p) {
        if (warp_n == p) {
#pragma unroll
            for (int mt = 0; mt < 2; ++mt)
#pragma unroll
                for (int j = 0; j < 8; ++j) {
                    int r0 = warp_m * 32 + mt * 16 + gid;
                    int cw = j * 8 + tig * 2;
                    float* st = stage + r0 * 66 + cw;
                    st[0] = acc[mt][j][0];
                    st[1] = acc[mt][j][1];
                    st[66 * 8] = acc[mt][j][2];
                    st[66 * 8 + 1] = acc[mt][j][3];
                }
        }
        __syncthreads();
        {
            int colw = tid & 63;
            int grp = tid >> 6;
            int gcol = n0 + p * 64 + colw;
            float bias = b2[gcol];
            int prev = -1;
            float mx = 0.f;
#pragma unroll 4
            for (int r = grp * 32; r < grp * 32 + 32; ++r) {
                int d = sdst[r];
                float v = fmaxf(stage[r * 66 + colw] + bias, 0.f);
                if (d == prev) {
                    mx = fmaxf(mx, v);
                } else {
                    if (prev >= 0)
                        atomicMax((int*)&AGG[(size_t)prev * NOUT + gcol], __float_as_int(mx));
                    prev = d;
                    mx = v;
                }
            }
            atomicMax((int*)&AGG[(size_t)prev * NOUT + gcol], __float_as_int(mx));
        }
        __syncthreads();
    }
}

// ---------------- dense head ----------------
__global__ void k_head(const float* __restrict__ W3, const float* __restrict__ b3,
                       const float* __restrict__ W4, const float* __restrict__ b4,
                       float* __restrict__ out) {
    __shared__ float sh[128];
    __shared__ float red[2];
    int n = blockIdx.x;
    int t = threadIdx.x;   // 64 threads
    sh[t]      = g_H2[n * 128 + t];
    sh[t + 64] = g_H2[n * 128 + 64 + t];
    __syncthreads();
    float s = b3[t];
#pragma unroll 8
    for (int k = 0; k < 128; k++) s += sh[k] * W3[k * 64 + t];
    s = fmaxf(s, 0.f);
    float p = s * W4[t];
#pragma unroll
    for (int off = 16; off > 0; off >>= 1) p += __shfl_down_sync(0xffffffffu, p, off);
    if ((t & 31) == 0) red[t >> 5] = p;
    __syncthreads();
    if (t == 0) {
        float z = red[0] + red[1] + b4[0];
        out[n] = 1.f / (1.f + expf(-z));
    }
}

// ---------------- launch ----------------
extern "C" void kernel_launch(void* const* d_in, const int* in_sizes, int n_in,
                              void* d_out, int out_size) {
    const float* x   = (const float*)d_in[0];
    const int*   ei  = (const int*)d_in[1];
    const int*   src = ei;
    const int*   dst = ei + N_EDGES;
    const float* W1a = (const float*)d_in[2];
    const float* b1a = (const float*)d_in[3];
    const float* W2a = (const float*)d_in[4];
    const float* b2a = (const float*)d_in[5];
    const float* W1b = (const float*)d_in[6];
    const float* b1b = (const float*)d_in[7];
    const float* W2b = (const float*)d_in[8];
    const float* b2b = (const float*)d_in[9];
    const float* W3  = (const float*)d_in[10];
    const float* b3  = (const float*)d_in[11];
    const float* W4  = (const float*)d_in[12];
    const float* b4  = (const float*)d_in[13];
    float* out = (float*)d_out;

    void *pC1, *pD1, *pH1, *pC2, *pD2, *pH2, *pWH1, *pWL1, *pWH2, *pWL2;
    cudaGetSymbolAddress(&pC1, g_C1);
    cudaGetSymbolAddress(&pD1, g_D1);
    cudaGetSymbolAddress(&pH1, g_H1);
    cudaGetSymbolAddress(&pC2, g_C2);
    cudaGetSymbolAddress(&pD2, g_D2);
    cudaGetSymbolAddress(&pH2, g_H2);
    cudaGetSymbolAddress(&pWH1, g_WH1);
    cudaGetSymbolAddress(&pWL1, g_WL1);
    cudaGetSymbolAddress(&pWH2, g_WH2);
    cudaGetSymbolAddress(&pWL2, g_WL2);

    cudaFuncSetAttribute(k_edge_mma<512, 256>, cudaFuncAttributeMaxDynamicSharedMemorySize, EDGE_SMEM);
    cudaFuncSetAttribute(k_edge_mma<256, 128>, cudaFuncAttributeMaxDynamicSharedMemorySize, EDGE_SMEM);

    // init + counting sort
    k_zero<<<512, 256>>>();
    k_hist<<<(N_EDGES + 255) / 256, 256>>>(dst);
    k_scan<<<1, 1024>>>();
    k_scatter<<<(N_EDGES + 255) / 256, 256>>>(src, dst);

    // weight prep (transpose + bf16 hi/lo split)
    k_prep<512, 256><<<(512 * 256 + 255) / 256, 256>>>(W2a, (__nv_bfloat16*)pWH1, (__nv_bfloat16*)pWL1);
    k_prep<256, 128><<<(256 * 128 + 255) / 256, 256>>>(W2b, (__nv_bfloat16*)pWH2, (__nv_bfloat16*)pWL2);

    // layer 1
    {
        dim3 g((N_NODES + 63) / 64, 512 / 64);
        k_node_dual<128, 512><<<g, 256>>>(x, W1a, (float*)pC1, (float*)pD1);
    }
    {
        dim3 g(N_EDGES / 128, 256 / 128);
        k_edge_mma<512, 256><<<g, 256, EDGE_SMEM>>>(
            (const float*)pC1, (const float*)pD1, b1a,
            (const __nv_bfloat16*)pWH1, (const __nv_bfloat16*)pWL1, b2a, (float*)pH1);
    }

    // layer 2
    {
        dim3 g((N_NODES + 63) / 64, 256 / 64);
        k_node_dual<256, 256><<<g, 256>>>((const float*)pH1, W1b, (float*)pC2, (float*)pD2);
    }
    {
        dim3 g(N_EDGES / 128, 128 / 128);
        k_edge_mma<256, 128><<<g, 256, EDGE_SMEM>>>(
            (const float*)pC2, (const float*)pD2, b1b,
            (const __nv_bfloat16*)pWH2, (const __nv_bfloat16*)pWL2, b2b, (float*)pH2);
    }

    // head
    k_head<<<N_NODES, 64>>>(W3, b3, W4, b4, out);
}

// round 6
// speedup vs baseline: 2.2346x; 1.3709x over previous
#include <cuda_runtime.h>
#include <cuda_fp16.h>
#include <stdint.h>
#include <math.h>

#define N_NODES 10000
#define N_EDGES 320000

// ---------------- scratch (static device allocations) ----------------
__device__ float g_C1[N_NODES * 512];
__device__ float g_D1[N_NODES * 512];
__device__ float g_H1[N_NODES * 256];
__device__ float g_C2[N_NODES * 256];
__device__ float g_D2[N_NODES * 256];
__device__ float g_H2[N_NODES * 128];
__device__ int   g_hist[N_NODES + 1];
__device__ int   g_cursor[N_NODES];
__device__ int   g_src_s[N_EDGES];
__device__ int   g_dst_s[N_EDGES];
// transposed fp16 weights (K-major [NOUT, K])
__device__ __half g_WT1[256 * 512];
__device__ __half g_WT2[128 * 256];

// ---------------- helpers ----------------
__device__ __forceinline__ void mma_f16(float* c,
    uint32_t a0, uint32_t a1, uint32_t a2, uint32_t a3,
    uint32_t b0, uint32_t b1) {
    asm volatile(
        "mma.sync.aligned.m16n8k16.row.col.f32.f16.f16.f32 "
        "{%0,%1,%2,%3}, {%4,%5,%6,%7}, {%8,%9}, {%0,%1,%2,%3};"
        : "+f"(c[0]), "+f"(c[1]), "+f"(c[2]), "+f"(c[3])
        : "r"(a0), "r"(a1), "r"(a2), "r"(a3), "r"(b0), "r"(b1));
}

// ---------------- init ----------------
__global__ void k_zero() {
    int stride = gridDim.x * blockDim.x;
    int i0 = blockIdx.x * blockDim.x + threadIdx.x;
    for (int j = i0; j < N_NODES * 256; j += stride) g_H1[j] = 0.f;
    for (int j = i0; j < N_NODES * 128; j += stride) g_H2[j] = 0.f;
    for (int j = i0; j <= N_NODES;      j += stride) g_hist[j] = 0;
    for (int j = i0; j < N_NODES;       j += stride) g_cursor[j] = 0;
}

// ---------------- counting sort by dst ----------------
__global__ void k_hist(const int* __restrict__ dst) {
    int e = blockIdx.x * blockDim.x + threadIdx.x;
    if (e < N_EDGES) atomicAdd(&g_hist[dst[e] + 1], 1);
}
__global__ void k_scan() {
    __shared__ int s[1024];
    __shared__ int carry;
    int tid = threadIdx.x;
    if (tid == 0) carry = 0;
    __syncthreads();
    for (int base = 0; base < N_NODES + 1; base += 1024) {
        int i = base + tid;
        int v = (i < N_NODES + 1) ? g_hist[i] : 0;
        s[tid] = v;
        __syncthreads();
        for (int off = 1; off < 1024; off <<= 1) {
            int t = (tid >= off) ? s[tid - off] : 0;
            __syncthreads();
            s[tid] += t;
            __syncthreads();
        }
        int out = s[tid] + carry;
        if (i < N_NODES + 1) g_hist[i] = out;
        __syncthreads();
        if (tid == 1023) carry = out;
        __syncthreads();
    }
}
__global__ void k_scatter(const int* __restrict__ src, const int* __restrict__ dst) {
    int e = blockIdx.x * blockDim.x + threadIdx.x;
    if (e < N_EDGES) {
        int d = dst[e];
        int pos = g_hist[d] + atomicAdd(&g_cursor[d], 1);
        g_src_s[pos] = src[e];
        g_dst_s[pos] = d;
    }
}

// ---------------- weight prep: W2 [K,NOUT] fp32 -> W2^T [NOUT,K] fp16 ----------------
template <int KW, int NOUT>
__global__ void k_prep(const float* __restrict__ W2, __half* __restrict__ WT) {
    int i = blockIdx.x * blockDim.x + threadIdx.x;
    if (i < KW * NOUT) {
        int n = i / KW, k = i % KW;
        WT[i] = __float2half_rn(W2[k * NOUT + n]);
    }
}

// ---------------- node dual GEMM: C = X@(Wtop-Wbot), D = X@Wbot ----------------
template <int K, int N>
__launch_bounds__(256)
__global__ void k_node_dual(const float* __restrict__ X, const float* __restrict__ W,
                            float* __restrict__ C, float* __restrict__ D) {
    __shared__ float As[16][68];
    __shared__ float Bd[16][64];
    __shared__ float Bb[16][64];
    int tid = threadIdx.x;
    int tx = tid & 15, ty = tid >> 4;
    int m0 = blockIdx.x * 64;
    int n0 = blockIdx.y * 64;
    float accC[4][4] = {};
    float accD[4][4] = {};
    for (int k0 = 0; k0 < K; k0 += 16) {
        {
            int m = tid >> 2;
            int kq = (tid & 3) * 4;
            int gm = m0 + m;
            float4 a = make_float4(0.f, 0.f, 0.f, 0.f);
            if (gm < N_NODES) a = *(const float4*)&X[gm * K + k0 + kq];
            As[kq + 0][m] = a.x; As[kq + 1][m] = a.y;
            As[kq + 2][m] = a.z; As[kq + 3][m] = a.w;
        }
        {
            int k  = tid >> 4;
            int nq = (tid & 15) * 4;
            float4 t = *(const float4*)&W[(k0 + k) * N + n0 + nq];
            float4 b = *(const float4*)&W[(K + k0 + k) * N + n0 + nq];
            *(float4*)&Bb[k][nq] = b;
            float4 dv = make_float4(t.x - b.x, t.y - b.y, t.z - b.z, t.w - b.w);
            *(float4*)&Bd[k][nq] = dv;
        }
        __syncthreads();
#pragma unroll
        for (int kk = 0; kk < 16; kk++) {
            float a[4];
#pragma unroll
            for (int i = 0; i < 4; i++) a[i] = As[kk][ty * 4 + i];
            float4 vd = *(float4*)&Bd[kk][tx * 4];
            float4 vb = *(float4*)&Bb[kk][tx * 4];
            float bd[4] = {vd.x, vd.y, vd.z, vd.w};
            float bb[4] = {vb.x, vb.y, vb.z, vb.w};
#pragma unroll
            for (int i = 0; i < 4; i++)
#pragma unroll
                for (int j = 0; j < 4; j++) {
                    accC[i][j] += a[i] * bd[j];
                    accD[i][j] += a[i] * bb[j];
                }
        }
        __syncthreads();
    }
#pragma unroll
    for (int i = 0; i < 4; i++) {
        int gm = m0 + ty * 4 + i;
        if (gm < N_NODES) {
            float4 c = make_float4(accC[i][0], accC[i][1], accC[i][2], accC[i][3]);
            float4 d = make_float4(accD[i][0], accD[i][1], accD[i][2], accD[i][3]);
            *(float4*)&C[gm * N + n0 + tx * 4] = c;
            *(float4*)&D[gm * N + n0 + tx * 4] = d;
        }
    }
}

// ---------------- fp16 mma.sync edge GEMM + segmented max ----------------
// Block: 256 thr (8 warps: 4 M x 2 N). Tile: 128 edges x 128 cols. K chunk 64.
// A = fp16(relu(C[dst]+D[src]+b1)); B = fp16 W2^T. Single-term fp16 MMA, fp32 acc.
// SMEM (bytes): sdst@0[512], ssrc@512[512], A@1024 (128 x 144B), B@19456 (128 x 144B)
// epilogue stage reuses @1024: 128 x 66 floats.
#define SM_SDST 0
#define SM_SSRC 512
#define SM_A    1024
#define SM_B    19456
#define SM_STG  1024
#define EDGE_SMEM 37888

template <int KW, int NOUT>
__global__ void __launch_bounds__(256, 2) k_edge_mma(
    const float* __restrict__ C, const float* __restrict__ D, const float* __restrict__ b1v,
    const __half* __restrict__ WT, const float* __restrict__ b2, float* __restrict__ AGG)
{
    extern __shared__ char smem[];
    const int tid = threadIdx.x;
    const int wid = tid >> 5, lid = tid & 31;
    const int warp_m = wid & 3, warp_n = wid >> 2;
    const int gid = lid >> 2, tig = lid & 3;

    int* sdst = (int*)(smem + SM_SDST);
    int* ssrc = (int*)(smem + SM_SSRC);

    const int e0 = blockIdx.x * 128;
    const int n0 = blockIdx.y * 128;
    if (tid < 128) {
        sdst[tid] = g_dst_s[e0 + tid];
        ssrc[tid] = g_src_s[e0 + tid];
    }
    __syncthreads();

    // fill assignment: 2 threads per row, 32 halves each
    const int fm = tid >> 1;
    const int fk = (tid & 1) * 32;
    const size_t rowC = (size_t)sdst[fm] * KW;
    const size_t rowD = (size_t)ssrc[fm] * KW;
    const size_t rowW = (size_t)(n0 + fm) * KW;

    float acc[2][8][4];
#pragma unroll
    for (int a = 0; a < 2; ++a)
#pragma unroll
        for (int b = 0; b < 8; ++b)
#pragma unroll
            for (int c = 0; c < 4; ++c) acc[a][b][c] = 0.f;

    constexpr int NCH = KW / 64;
#pragma unroll 1
    for (int ch = 0; ch < NCH; ++ch) {
        const int k0 = ch * 64 + fk;
        // ---- A tile: fused gather + bias + relu + fp16 convert (32 halves/thread)
        {
            const float* cp = C + rowC + k0;
            const float* dp = D + rowD + k0;
            const float* bp = b1v + k0;
            uint32_t h[16];
#pragma unroll
            for (int g = 0; g < 8; ++g) {
                float4 cv = *(const float4*)(cp + g * 4);
                float4 dv = *(const float4*)(dp + g * 4);
                float4 bv = *(const float4*)(bp + g * 4);
                float v0 = fmaxf(cv.x + dv.x + bv.x, 0.f);
                float v1 = fmaxf(cv.y + dv.y + bv.y, 0.f);
                float v2 = fmaxf(cv.z + dv.z + bv.z, 0.f);
                float v3 = fmaxf(cv.w + dv.w + bv.w, 0.f);
                __half2 p0 = __floats2half2_rn(v0, v1);
                __half2 p1 = __floats2half2_rn(v2, v3);
                h[g * 2]     = *reinterpret_cast<uint32_t*>(&p0);
                h[g * 2 + 1] = *reinterpret_cast<uint32_t*>(&p1);
            }
            char* pa = smem + SM_A + fm * 144 + fk * 2;
            *(uint4*)pa        = make_uint4(h[0],  h[1],  h[2],  h[3]);
            *(uint4*)(pa + 16) = make_uint4(h[4],  h[5],  h[6],  h[7]);
            *(uint4*)(pa + 32) = make_uint4(h[8],  h[9],  h[10], h[11]);
            *(uint4*)(pa + 48) = make_uint4(h[12], h[13], h[14], h[15]);
        }
        // ---- B tile: fp16 weights (32 halves/thread)
        {
            const uint4* wp = (const uint4*)(WT + rowW + k0);
            char* pb = smem + SM_B + fm * 144 + fk * 2;
            *(uint4*)pb        = wp[0];
            *(uint4*)(pb + 16) = wp[1];
            *(uint4*)(pb + 32) = wp[2];
            *(uint4*)(pb + 48) = wp[3];
        }
        __syncthreads();

        // ---- 4 k-steps of 16
#pragma unroll
        for (int ks = 0; ks < 4; ++ks) {
            const int koff = ks * 32 + tig * 4;   // byte offset of k-pair
            uint32_t a[2][4];
#pragma unroll
            for (int mt = 0; mt < 2; ++mt) {
                int r = warp_m * 32 + mt * 16 + gid;
                const char* base = smem + SM_A + r * 144;
                a[mt][0] = *(const uint32_t*)(base + koff);
                a[mt][1] = *(const uint32_t*)(base + 8 * 144 + koff);
                a[mt][2] = *(const uint32_t*)(base + koff + 16);
                a[mt][3] = *(const uint32_t*)(base + 8 * 144 + koff + 16);
            }
#pragma unroll
            for (int j = 0; j < 8; ++j) {
                int n = warp_n * 64 + j * 8 + gid;
                const char* bb = smem + SM_B + n * 144;
                uint32_t b0 = *(const uint32_t*)(bb + koff);
                uint32_t b1 = *(const uint32_t*)(bb + koff + 16);
                mma_f16(acc[0][j], a[0][0], a[0][1], a[0][2], a[0][3], b0, b1);
                mma_f16(acc[1][j], a[1][0], a[1][1], a[1][2], a[1][3], b0, b1);
            }
        }
        __syncthreads();
    }

    // ---- epilogue: stage to SMEM, bias+relu, segmented max over sorted dst
    float* stage = (float*)(smem + SM_STG);
#pragma unroll 1
    for (int p = 0; p < 2; ++p) {
        if (warp_n == p) {
#pragma unroll
            for (int mt = 0; mt < 2; ++mt)
#pragma unroll
                for (int j = 0; j < 8; ++j) {
                    int r0 = warp_m * 32 + mt * 16 + gid;
                    int cw = j * 8 + tig * 2;
                    float* st = stage + r0 * 66 + cw;
                    st[0] = acc[mt][j][0];
                    st[1] = acc[mt][j][1];
                    st[66 * 8] = acc[mt][j][2];
                    st[66 * 8 + 1] = acc[mt][j][3];
                }
        }
        __syncthreads();
        {
            int colw = tid & 63;
            int grp = tid >> 6;
            int gcol = n0 + p * 64 + colw;
            float bias = b2[gcol];
            int prev = -1;
            float mx = 0.f;
#pragma unroll 4
            for (int r = grp * 32; r < grp * 32 + 32; ++r) {
                int d = sdst[r];
                float v = fmaxf(stage[r * 66 + colw] + bias, 0.f);
                if (d == prev) {
                    mx = fmaxf(mx, v);
                } else {
                    if (prev >= 0)
                        atomicMax((int*)&AGG[(size_t)prev * NOUT + gcol], __float_as_int(mx));
                    prev = d;
                    mx = v;
                }
            }
            atomicMax((int*)&AGG[(size_t)prev * NOUT + gcol], __float_as_int(mx));
        }
        __syncthreads();
    }
}

// ---------------- dense head ----------------
__global__ void k_head(const float* __restrict__ W3, const float* __restrict__ b3,
                       const float* __restrict__ W4, const float* __restrict__ b4,
                       float* __restrict__ out) {
    __shared__ float sh[128];
    __shared__ float red[2];
    int n = blockIdx.x;
    int t = threadIdx.x;   // 64 threads
    sh[t]      = g_H2[n * 128 + t];
    sh[t + 64] = g_H2[n * 128 + 64 + t];
    __syncthreads();
    float s = b3[t];
#pragma unroll 8
    for (int k = 0; k < 128; k++) s += sh[k] * W3[k * 64 + t];
    s = fmaxf(s, 0.f);
    float p = s * W4[t];
#pragma unroll
    for (int off = 16; off > 0; off >>= 1) p += __shfl_down_sync(0xffffffffu, p, off);
    if ((t & 31) == 0) red[t >> 5] = p;
    __syncthreads();
    if (t == 0) {
        float z = red[0] + red[1] + b4[0];
        out[n] = 1.f / (1.f + expf(-z));
    }
}

// ---------------- launch ----------------
extern "C" void kernel_launch(void* const* d_in, const int* in_sizes, int n_in,
                              void* d_out, int out_size) {
    const float* x   = (const float*)d_in[0];
    const int*   ei  = (const int*)d_in[1];
    const int*   src = ei;
    const int*   dst = ei + N_EDGES;
    const float* W1a = (const float*)d_in[2];
    const float* b1a = (const float*)d_in[3];
    const float* W2a = (const float*)d_in[4];
    const float* b2a = (const float*)d_in[5];
    const float* W1b = (const float*)d_in[6];
    const float* b1b = (const float*)d_in[7];
    const float* W2b = (const float*)d_in[8];
    const float* b2b = (const float*)d_in[9];
    const float* W3  = (const float*)d_in[10];
    const float* b3  = (const float*)d_in[11];
    const float* W4  = (const float*)d_in[12];
    const float* b4  = (const float*)d_in[13];
    float* out = (float*)d_out;

    void *pC1, *pD1, *pH1, *pC2, *pD2, *pH2, *pWT1, *pWT2;
    cudaGetSymbolAddress(&pC1, g_C1);
    cudaGetSymbolAddress(&pD1, g_D1);
    cudaGetSymbolAddress(&pH1, g_H1);
    cudaGetSymbolAddress(&pC2, g_C2);
    cudaGetSymbolAddress(&pD2, g_D2);
    cudaGetSymbolAddress(&pH2, g_H2);
    cudaGetSymbolAddress(&pWT1, g_WT1);
    cudaGetSymbolAddress(&pWT2, g_WT2);

    cudaFuncSetAttribute(k_edge_mma<512, 256>, cudaFuncAttributeMaxDynamicSharedMemorySize, EDGE_SMEM);
    cudaFuncSetAttribute(k_edge_mma<256, 128>, cudaFuncAttributeMaxDynamicSharedMemorySize, EDGE_SMEM);

    // init + counting sort
    k_zero<<<512, 256>>>();
    k_hist<<<(N_EDGES + 255) / 256, 256>>>(dst);
    k_scan<<<1, 1024>>>();
    k_scatter<<<(N_EDGES + 255) / 256, 256>>>(src, dst);

    // weight prep (transpose + fp16)
    k_prep<512, 256><<<(512 * 256 + 255) / 256, 256>>>(W2a, (__half*)pWT1);
    k_prep<256, 128><<<(256 * 128 + 255) / 256, 256>>>(W2b, (__half*)pWT2);

    // layer 1
    {
        dim3 g((N_NODES + 63) / 64, 512 / 64);
        k_node_dual<128, 512><<<g, 256>>>(x, W1a, (float*)pC1, (float*)pD1);
    }
    {
        dim3 g(N_EDGES / 128, 256 / 128);
        k_edge_mma<512, 256><<<g, 256, EDGE_SMEM>>>(
            (const float*)pC1, (const float*)pD1, b1a,
            (const __half*)pWT1, b2a, (float*)pH1);
    }

    // layer 2
    {
        dim3 g((N_NODES + 63) / 64, 256 / 64);
        k_node_dual<256, 256><<<g, 256>>>((const float*)pH1, W1b, (float*)pC2, (float*)pD2);
    }
    {
        dim3 g(N_EDGES / 128, 128 / 128);
        k_edge_mma<256, 128><<<g, 256, EDGE_SMEM>>>(
            (const float*)pC2, (const float*)pD2, b1b,
            (const __half*)pWT2, b2b, (float*)pH2);
    }

    // head
    k_head<<<N_NODES, 64>>>(W3, b3, W4, b4, out);
}

// round 7
// speedup vs baseline: 3.5466x; 1.5871x over previous
#include <cuda_runtime.h>
#include <cuda_fp16.h>
#include <stdint.h>
#include <math.h>

#define N_NODES 10000
#define N_EDGES 320000

// ---------------- scratch (static device allocations) ----------------
__device__ __half g_C1[N_NODES * 512];   // fp16: x@(W1top-W1bot) + b1
__device__ __half g_D1[N_NODES * 512];   // fp16: x@W1bot
__device__ float  g_H1[N_NODES * 256];
__device__ __half g_C2[N_NODES * 256];
__device__ __half g_D2[N_NODES * 256];
__device__ float  g_H2[N_NODES * 128];
__device__ int    g_hist[N_NODES + 1];
__device__ int    g_cursor[N_NODES];
__device__ int    g_src_s[N_EDGES];
__device__ int    g_dst_s[N_EDGES];
// transposed fp16 weights (K-major [NOUT, K])
__device__ __half g_WT1[256 * 512];
__device__ __half g_WT2[128 * 256];

// ---------------- helpers ----------------
__device__ __forceinline__ void mma_f16(float* c,
    uint32_t a0, uint32_t a1, uint32_t a2, uint32_t a3,
    uint32_t b0, uint32_t b1) {
    asm volatile(
        "mma.sync.aligned.m16n8k16.row.col.f32.f16.f16.f32 "
        "{%0,%1,%2,%3}, {%4,%5,%6,%7}, {%8,%9}, {%0,%1,%2,%3};"
        : "+f"(c[0]), "+f"(c[1]), "+f"(c[2]), "+f"(c[3])
        : "r"(a0), "r"(a1), "r"(a2), "r"(a3), "r"(b0), "r"(b1));
}

// relu(a + b) on packed half2 (as uint32)
__device__ __forceinline__ uint32_t haddrelu2(uint32_t a, uint32_t b) {
    __half2 av = *reinterpret_cast<__half2*>(&a);
    __half2 bv = *reinterpret_cast<__half2*>(&b);
    __half2 r = __hmax2(__hadd2(av, bv), __float2half2_rn(0.f));
    return *reinterpret_cast<uint32_t*>(&r);
}

// ---------------- init ----------------
__global__ void k_zero() {
    int stride = gridDim.x * blockDim.x;
    int i0 = blockIdx.x * blockDim.x + threadIdx.x;
    for (int j = i0; j < N_NODES * 256; j += stride) g_H1[j] = 0.f;
    for (int j = i0; j < N_NODES * 128; j += stride) g_H2[j] = 0.f;
    for (int j = i0; j <= N_NODES;      j += stride) g_hist[j] = 0;
    for (int j = i0; j < N_NODES;       j += stride) g_cursor[j] = 0;
}

// ---------------- counting sort by dst ----------------
__global__ void k_hist(const int* __restrict__ dst) {
    int e = blockIdx.x * blockDim.x + threadIdx.x;
    if (e < N_EDGES) atomicAdd(&g_hist[dst[e] + 1], 1);
}
__global__ void k_scan() {
    __shared__ int s[1024];
    __shared__ int carry;
    int tid = threadIdx.x;
    if (tid == 0) carry = 0;
    __syncthreads();
    for (int base = 0; base < N_NODES + 1; base += 1024) {
        int i = base + tid;
        int v = (i < N_NODES + 1) ? g_hist[i] : 0;
        s[tid] = v;
        __syncthreads();
        for (int off = 1; off < 1024; off <<= 1) {
            int t = (tid >= off) ? s[tid - off] : 0;
            __syncthreads();
            s[tid] += t;
            __syncthreads();
        }
        int out = s[tid] + carry;
        if (i < N_NODES + 1) g_hist[i] = out;
        __syncthreads();
        if (tid == 1023) carry = out;
        __syncthreads();
    }
}
__global__ void k_scatter(const int* __restrict__ src, const int* __restrict__ dst) {
    int e = blockIdx.x * blockDim.x + threadIdx.x;
    if (e < N_EDGES) {
        int d = dst[e];
        int pos = g_hist[d] + atomicAdd(&g_cursor[d], 1);
        g_src_s[pos] = src[e];
        g_dst_s[pos] = d;
    }
}

// ---------------- weight prep: W2 [K,NOUT] fp32 -> W2^T [NOUT,K] fp16 ----------------
template <int KW, int NOUT>
__global__ void k_prep(const float* __restrict__ W2, __half* __restrict__ WT) {
    int i = blockIdx.x * blockDim.x + threadIdx.x;
    if (i < KW * NOUT) {
        int n = i / KW, k = i % KW;
        WT[i] = __float2half_rn(W2[k * NOUT + n]);
    }
}

// ---------------- node dual GEMM -> fp16: C = X@(Wtop-Wbot)+b1, D = X@Wbot ----------------
template <int K, int N>
__launch_bounds__(256)
__global__ void k_node_dual(const float* __restrict__ X, const float* __restrict__ W,
                            const float* __restrict__ b1,
                            __half* __restrict__ C, __half* __restrict__ D) {
    __shared__ float As[16][68];
    __shared__ float Bd[16][64];
    __shared__ float Bb[16][64];
    int tid = threadIdx.x;
    int tx = tid & 15, ty = tid >> 4;
    int m0 = blockIdx.x * 64;
    int n0 = blockIdx.y * 64;
    float accC[4][4] = {};
    float accD[4][4] = {};
    for (int k0 = 0; k0 < K; k0 += 16) {
        {
            int m = tid >> 2;
            int kq = (tid & 3) * 4;
            int gm = m0 + m;
            float4 a = make_float4(0.f, 0.f, 0.f, 0.f);
            if (gm < N_NODES) a = *(const float4*)&X[gm * K + k0 + kq];
            As[kq + 0][m] = a.x; As[kq + 1][m] = a.y;
            As[kq + 2][m] = a.z; As[kq + 3][m] = a.w;
        }
        {
            int k  = tid >> 4;
            int nq = (tid & 15) * 4;
            float4 t = *(const float4*)&W[(k0 + k) * N + n0 + nq];
            float4 b = *(const float4*)&W[(K + k0 + k) * N + n0 + nq];
            *(float4*)&Bb[k][nq] = b;
            float4 dv = make_float4(t.x - b.x, t.y - b.y, t.z - b.z, t.w - b.w);
            *(float4*)&Bd[k][nq] = dv;
        }
        __syncthreads();
#pragma unroll
        for (int kk = 0; kk < 16; kk++) {
            float a[4];
#pragma unroll
            for (int i = 0; i < 4; i++) a[i] = As[kk][ty * 4 + i];
            float4 vd = *(float4*)&Bd[kk][tx * 4];
            float4 vb = *(float4*)&Bb[kk][tx * 4];
            float bd[4] = {vd.x, vd.y, vd.z, vd.w};
            float bb[4] = {vb.x, vb.y, vb.z, vb.w};
#pragma unroll
            for (int i = 0; i < 4; i++)
#pragma unroll
                for (int j = 0; j < 4; j++) {
                    accC[i][j] += a[i] * bd[j];
                    accD[i][j] += a[i] * bb[j];
                }
        }
        __syncthreads();
    }
    float4 bias = *(const float4*)&b1[n0 + tx * 4];
#pragma unroll
    for (int i = 0; i < 4; i++) {
        int gm = m0 + ty * 4 + i;
        if (gm < N_NODES) {
            __half2 c0 = __floats2half2_rn(accC[i][0] + bias.x, accC[i][1] + bias.y);
            __half2 c1 = __floats2half2_rn(accC[i][2] + bias.z, accC[i][3] + bias.w);
            __half2 d0 = __floats2half2_rn(accD[i][0], accD[i][1]);
            __half2 d1 = __floats2half2_rn(accD[i][2], accD[i][3]);
            uint2 cv = make_uint2(*(uint32_t*)&c0, *(uint32_t*)&c1);
            uint2 dv = make_uint2(*(uint32_t*)&d0, *(uint32_t*)&d1);
            *(uint2*)&C[(size_t)gm * N + n0 + tx * 4] = cv;
            *(uint2*)&D[(size_t)gm * N + n0 + tx * 4] = dv;
        }
    }
}

// ---------------- fp16 mma.sync edge GEMM + segmented max (pipelined) ----------------
// Block: 256 thr (8 warps: 4 M x 2 N). Tile: 128 edges x 128 cols. K chunk 64.
// A = relu(C16[dst] + D16[src]) (bias pre-folded into C16); B = fp16 W2^T.
// C/D gathers for the NEXT chunk are prefetched into registers during the MMA phase.
#define SM_SDST 0
#define SM_SSRC 512
#define SM_A    1024
#define SM_B    19456
#define SM_STG  1024
#define EDGE_SMEM 37888

template <int KW, int NOUT>
__global__ void __launch_bounds__(256, 2) k_edge_mma(
    const __half* __restrict__ C, const __half* __restrict__ D,
    const __half* __restrict__ WT, const float* __restrict__ b2, float* __restrict__ AGG)
{
    extern __shared__ char smem[];
    const int tid = threadIdx.x;
    const int wid = tid >> 5, lid = tid & 31;
    const int warp_m = wid & 3, warp_n = wid >> 2;
    const int gid = lid >> 2, tig = lid & 3;

    int* sdst = (int*)(smem + SM_SDST);
    int* ssrc = (int*)(smem + SM_SSRC);

    const int e0 = blockIdx.x * 128;
    const int n0 = blockIdx.y * 128;
    if (tid < 128) {
        sdst[tid] = g_dst_s[e0 + tid];
        ssrc[tid] = g_src_s[e0 + tid];
    }
    __syncthreads();

    // fill assignment: 2 threads per row, 32 halves (64B) each
    const int fm = tid >> 1;
    const int fk = (tid & 1) * 32;          // half-element offset within 64-chunk
    const __half* rowC = C + (size_t)sdst[fm] * KW + fk;
    const __half* rowD = D + (size_t)ssrc[fm] * KW + fk;
    const __half* rowW = WT + (size_t)(n0 + fm) * KW + fk;

    float acc[2][8][4];
#pragma unroll
    for (int a = 0; a < 2; ++a)
#pragma unroll
        for (int b = 0; b < 8; ++b)
#pragma unroll
            for (int c = 0; c < 4; ++c) acc[a][b][c] = 0.f;

    constexpr int NCH = KW / 64;
    uint4 pc[4], pd[4];
    {   // prologue: prefetch chunk 0
        const uint4* cp = (const uint4*)rowC;
        const uint4* dp = (const uint4*)rowD;
#pragma unroll
        for (int q = 0; q < 4; ++q) { pc[q] = cp[q]; pd[q] = dp[q]; }
    }

#pragma unroll 1
    for (int ch = 0; ch < NCH; ++ch) {
        // ---- B tile LDG first (latency hidden by A convert below)
        const uint4* wp = (const uint4*)(rowW + ch * 64);
        uint4 w0 = wp[0], w1 = wp[1], w2 = wp[2], w3 = wp[3];

        // ---- A tile: relu(C+D) on half2, from prefetched registers
        {
            uint4 ao[4];
#pragma unroll
            for (int q = 0; q < 4; ++q) {
                ao[q].x = haddrelu2(pc[q].x, pd[q].x);
                ao[q].y = haddrelu2(pc[q].y, pd[q].y);
                ao[q].z = haddrelu2(pc[q].z, pd[q].z);
                ao[q].w = haddrelu2(pc[q].w, pd[q].w);
            }
            char* pa = smem + SM_A + fm * 144 + fk * 2;
            *(uint4*)pa        = ao[0];
            *(uint4*)(pa + 16) = ao[1];
            *(uint4*)(pa + 32) = ao[2];
            *(uint4*)(pa + 48) = ao[3];
        }
        {
            char* pb = smem + SM_B + fm * 144 + fk * 2;
            *(uint4*)pb        = w0;
            *(uint4*)(pb + 16) = w1;
            *(uint4*)(pb + 32) = w2;
            *(uint4*)(pb + 48) = w3;
        }
        __syncthreads();

        // ---- prefetch next chunk C/D (overlaps MMA below)
        if (ch + 1 < NCH) {
            const uint4* cp = (const uint4*)(rowC + (ch + 1) * 64);
            const uint4* dp = (const uint4*)(rowD + (ch + 1) * 64);
#pragma unroll
            for (int q = 0; q < 4; ++q) { pc[q] = cp[q]; pd[q] = dp[q]; }
        }

        // ---- 4 k-steps of 16
#pragma unroll
        for (int ks = 0; ks < 4; ++ks) {
            const int koff = ks * 32 + tig * 4;   // byte offset of k-pair
            uint32_t a[2][4];
#pragma unroll
            for (int mt = 0; mt < 2; ++mt) {
                int r = warp_m * 32 + mt * 16 + gid;
                const char* base = smem + SM_A + r * 144;
                a[mt][0] = *(const uint32_t*)(base + koff);
                a[mt][1] = *(const uint32_t*)(base + 8 * 144 + koff);
                a[mt][2] = *(const uint32_t*)(base + koff + 16);
                a[mt][3] = *(const uint32_t*)(base + 8 * 144 + koff + 16);
            }
#pragma unroll
            for (int j = 0; j < 8; ++j) {
                int n = warp_n * 64 + j * 8 + gid;
                const char* bb = smem + SM_B + n * 144;
                uint32_t b0 = *(const uint32_t*)(bb + koff);
                uint32_t b1 = *(const uint32_t*)(bb + koff + 16);
                mma_f16(acc[0][j], a[0][0], a[0][1], a[0][2], a[0][3], b0, b1);
                mma_f16(acc[1][j], a[1][0], a[1][1], a[1][2], a[1][3], b0, b1);
            }
        }
        __syncthreads();
    }

    // ---- epilogue: stage to SMEM, bias+relu, segmented max over sorted dst
    float* stage = (float*)(smem + SM_STG);
#pragma unroll 1
    for (int p = 0; p < 2; ++p) {
        if (warp_n == p) {
#pragma unroll
            for (int mt = 0; mt < 2; ++mt)
#pragma unroll
                for (int j = 0; j < 8; ++j) {
                    int r0 = warp_m * 32 + mt * 16 + gid;
                    int cw = j * 8 + tig * 2;
                    float* st = stage + r0 * 66 + cw;
                    st[0] = acc[mt][j][0];
                    st[1] = acc[mt][j][1];
                    st[66 * 8] = acc[mt][j][2];
                    st[66 * 8 + 1] = acc[mt][j][3];
                }
        }
        __syncthreads();
        {
            int colw = tid & 63;
            int grp = tid >> 6;
            int gcol = n0 + p * 64 + colw;
            float bias = b2[gcol];
            int prev = -1;
            float mx = 0.f;
#pragma unroll 4
            for (int r = grp * 32; r < grp * 32 + 32; ++r) {
                int d = sdst[r];
                float v = fmaxf(stage[r * 66 + colw] + bias, 0.f);
                if (d == prev) {
                    mx = fmaxf(mx, v);
                } else {
                    if (prev >= 0)
                        atomicMax((int*)&AGG[(size_t)prev * NOUT + gcol], __float_as_int(mx));
                    prev = d;
                    mx = v;
                }
            }
            atomicMax((int*)&AGG[(size_t)prev * NOUT + gcol], __float_as_int(mx));
        }
        __syncthreads();
    }
}

// ---------------- dense head ----------------
__global__ void k_head(const float* __restrict__ W3, const float* __restrict__ b3,
                       const float* __restrict__ W4, const float* __restrict__ b4,
                       float* __restrict__ out) {
    __shared__ float sh[128];
    __shared__ float red[2];
    int n = blockIdx.x;
    int t = threadIdx.x;   // 64 threads
    sh[t]      = g_H2[n * 128 + t];
    sh[t + 64] = g_H2[n * 128 + 64 + t];
    __syncthreads();
    float s = b3[t];
#pragma unroll 8
    for (int k = 0; k < 128; k++) s += sh[k] * W3[k * 64 + t];
    s = fmaxf(s, 0.f);
    float p = s * W4[t];
#pragma unroll
    for (int off = 16; off > 0; off >>= 1) p += __shfl_down_sync(0xffffffffu, p, off);
    if ((t & 31) == 0) red[t >> 5] = p;
    __syncthreads();
    if (t == 0) {
        float z = red[0] + red[1] + b4[0];
        out[n] = 1.f / (1.f + expf(-z));
    }
}

// ---------------- launch ----------------
extern "C" void kernel_launch(void* const* d_in, const int* in_sizes, int n_in,
                              void* d_out, int out_size) {
    const float* x   = (const float*)d_in[0];
    const int*   ei  = (const int*)d_in[1];
    const int*   src = ei;
    const int*   dst = ei + N_EDGES;
    const float* W1a = (const float*)d_in[2];
    const float* b1a = (const float*)d_in[3];
    const float* W2a = (const float*)d_in[4];
    const float* b2a = (const float*)d_in[5];
    const float* W1b = (const float*)d_in[6];
    const float* b1b = (const float*)d_in[7];
    const float* W2b = (const float*)d_in[8];
    const float* b2b = (const float*)d_in[9];
    const float* W3  = (const float*)d_in[10];
    const float* b3  = (const float*)d_in[11];
    const float* W4  = (const float*)d_in[12];
    const float* b4  = (const float*)d_in[13];
    float* out = (float*)d_out;

    void *pC1, *pD1, *pH1, *pC2, *pD2, *pH2, *pWT1, *pWT2;
    cudaGetSymbolAddress(&pC1, g_C1);
    cudaGetSymbolAddress(&pD1, g_D1);
    cudaGetSymbolAddress(&pH1, g_H1);
    cudaGetSymbolAddress(&pC2, g_C2);
    cudaGetSymbolAddress(&pD2, g_D2);
    cudaGetSymbolAddress(&pH2, g_H2);
    cudaGetSymbolAddress(&pWT1, g_WT1);
    cudaGetSymbolAddress(&pWT2, g_WT2);

    cudaFuncSetAttribute(k_edge_mma<512, 256>, cudaFuncAttributeMaxDynamicSharedMemorySize, EDGE_SMEM);
    cudaFuncSetAttribute(k_edge_mma<256, 128>, cudaFuncAttributeMaxDynamicSharedMemorySize, EDGE_SMEM);

    // init + counting sort
    k_zero<<<512, 256>>>();
    k_hist<<<(N_EDGES + 255) / 256, 256>>>(dst);
    k_scan<<<1, 1024>>>();
    k_scatter<<<(N_EDGES + 255) / 256, 256>>>(src, dst);

    // weight prep (transpose + fp16)
    k_prep<512, 256><<<(512 * 256 + 255) / 256, 256>>>(W2a, (__half*)pWT1);
    k_prep<256, 128><<<(256 * 128 + 255) / 256, 256>>>(W2b, (__half*)pWT2);

    // layer 1
    {
        dim3 g((N_NODES + 63) / 64, 512 / 64);
        k_node_dual<128, 512><<<g, 256>>>(x, W1a, b1a, (__half*)pC1, (__half*)pD1);
    }
    {
        dim3 g(N_EDGES / 128, 256 / 128);
        k_edge_mma<512, 256><<<g, 256, EDGE_SMEM>>>(
            (const __half*)pC1, (const __half*)pD1,
            (const __half*)pWT1, b2a, (float*)pH1);
    }

    // layer 2
    {
        dim3 g((N_NODES + 63) / 64, 256 / 64);
        k_node_dual<256, 256><<<g, 256>>>((const float*)pH1, W1b, b1b, (__half*)pC2, (__half*)pD2);
    }
    {
        dim3 g(N_EDGES / 128, 128 / 128);
        k_edge_mma<256, 128><<<g, 256, EDGE_SMEM>>>(
            (const __half*)pC2, (const __half*)pD2,
            (const __half*)pWT2, b2b, (float*)pH2);
    }

    // head
    k_head<<<N_NODES, 64>>>(W3, b3, W4, b4, out);
}

// round 8
// speedup vs baseline: 3.7903x; 1.0687x over previous
#include <cuda_runtime.h>
#include <cuda_fp16.h>
#include <stdint.h>
#include <math.h>

#define N_NODES 10000
#define N_EDGES 320000

// ---------------- scratch (static device allocations) ----------------
__device__ __half g_C1[N_NODES * 512];   // fp16: x@(W1top-W1bot) + b1
__device__ __half g_D1[N_NODES * 512];   // fp16: x@W1bot
__device__ float  g_H1[N_NODES * 256];
__device__ __half g_C2[N_NODES * 256];
__device__ __half g_D2[N_NODES * 256];
__device__ float  g_H2[N_NODES * 128];
__device__ int    g_hist[N_NODES + 1];
__device__ int    g_cursor[N_NODES];
__device__ int    g_src_s[N_EDGES];
__device__ int    g_dst_s[N_EDGES];
// transposed fp16 weights (K-major [NOUT, K]) for edge second-layer GEMMs
__device__ __half g_WT1[256 * 512];
__device__ __half g_WT2[128 * 256];
// dual first-layer weights: rows [0,NOUT) = (Wtop-Wbot)^T, rows [NOUT,2NOUT) = Wbot^T
__device__ __half g_WTD1[1024 * 128];
__device__ __half g_WTD2[512 * 256];

// ---------------- helpers ----------------
__device__ __forceinline__ uint32_t smem_u32(const void* p) {
    uint32_t a;
    asm("{ .reg .u64 t; cvta.to.shared.u64 t, %1; cvt.u32.u64 %0, t; }" : "=r"(a) : "l"(p));
    return a;
}
__device__ __forceinline__ void mma_f16(float* c,
    uint32_t a0, uint32_t a1, uint32_t a2, uint32_t a3,
    uint32_t b0, uint32_t b1) {
    asm volatile(
        "mma.sync.aligned.m16n8k16.row.col.f32.f16.f16.f32 "
        "{%0,%1,%2,%3}, {%4,%5,%6,%7}, {%8,%9}, {%0,%1,%2,%3};"
        : "+f"(c[0]), "+f"(c[1]), "+f"(c[2]), "+f"(c[3])
        : "r"(a0), "r"(a1), "r"(a2), "r"(a3), "r"(b0), "r"(b1));
}
__device__ __forceinline__ uint32_t haddrelu2(uint32_t a, uint32_t b) {
    __half2 av = *reinterpret_cast<__half2*>(&a);
    __half2 bv = *reinterpret_cast<__half2*>(&b);
    __half2 r = __hmax2(__hadd2(av, bv), __float2half2_rn(0.f));
    return *reinterpret_cast<uint32_t*>(&r);
}
__device__ __forceinline__ void cp16(uint32_t dst, const void* src) {
    asm volatile("cp.async.ca.shared.global [%0], [%1], 16;" :: "r"(dst), "l"(src) : "memory");
}
__device__ __forceinline__ void cp_commit() {
    asm volatile("cp.async.commit_group;" ::: "memory");
}
__device__ __forceinline__ void cp_wait_all() {
    asm volatile("cp.async.wait_group 0;" ::: "memory");
}

// ---------------- init ----------------
__global__ void k_zero() {
    int stride = gridDim.x * blockDim.x;
    int i0 = blockIdx.x * blockDim.x + threadIdx.x;
    for (int j = i0; j < N_NODES * 256; j += stride) g_H1[j] = 0.f;
    for (int j = i0; j < N_NODES * 128; j += stride) g_H2[j] = 0.f;
    for (int j = i0; j <= N_NODES;      j += stride) g_hist[j] = 0;
    for (int j = i0; j < N_NODES;       j += stride) g_cursor[j] = 0;
}

// ---------------- counting sort by dst ----------------
__global__ void k_hist(const int* __restrict__ dst) {
    int e = blockIdx.x * blockDim.x + threadIdx.x;
    if (e < N_EDGES) atomicAdd(&g_hist[dst[e] + 1], 1);
}
__global__ void k_scan() {
    __shared__ int s[1024];
    __shared__ int carry;
    int tid = threadIdx.x;
    if (tid == 0) carry = 0;
    __syncthreads();
    for (int base = 0; base < N_NODES + 1; base += 1024) {
        int i = base + tid;
        int v = (i < N_NODES + 1) ? g_hist[i] : 0;
        s[tid] = v;
        __syncthreads();
        for (int off = 1; off < 1024; off <<= 1) {
            int t = (tid >= off) ? s[tid - off] : 0;
            __syncthreads();
            s[tid] += t;
            __syncthreads();
        }
        int out = s[tid] + carry;
        if (i < N_NODES + 1) g_hist[i] = out;
        __syncthreads();
        if (tid == 1023) carry = out;
        __syncthreads();
    }
}
__global__ void k_scatter(const int* __restrict__ src, const int* __restrict__ dst) {
    int e = blockIdx.x * blockDim.x + threadIdx.x;
    if (e < N_EDGES) {
        int d = dst[e];
        int pos = g_hist[d] + atomicAdd(&g_cursor[d], 1);
        g_src_s[pos] = src[e];
        g_dst_s[pos] = d;
    }
}

// ---------------- weight prep ----------------
// W2 [K,NOUT] fp32 -> W2^T [NOUT,K] fp16
template <int KW, int NOUT>
__global__ void k_prep(const float* __restrict__ W2, __half* __restrict__ WT) {
    int i = blockIdx.x * blockDim.x + threadIdx.x;
    if (i < KW * NOUT) {
        int n = i / KW, k = i % KW;
        WT[i] = __float2half_rn(W2[k * NOUT + n]);
    }
}
// W1 [2K,NOUT] fp32 -> dual transposed fp16 [2NOUT, K]
template <int K, int NOUT>
__global__ void k_prep_dual(const float* __restrict__ W1, __half* __restrict__ WT) {
    int i = blockIdx.x * blockDim.x + threadIdx.x;
    if (i < NOUT * K) {
        int n = i / K, k = i % K;
        float top = W1[k * NOUT + n];
        float bot = W1[(K + k) * NOUT + n];
        WT[(size_t)n * K + k] = __float2half_rn(top - bot);
        WT[(size_t)(NOUT + n) * K + k] = __float2half_rn(bot);
    }
}

// ---------------- node fp16 MMA GEMM: [C | D] = fp16(X) @ WTdual^T ----------------
// grid(ceil(N/128), 2*NOUT/128). Tile 128 nodes x 128 out-cols. K chunk 64.
// Writes C (cols < NOUT, +b1) or D (cols >= NOUT) as fp16, no relu.
#define NODE_SMEM 36864   // A@0 (128x144), B@18432 (128x144)

template <int K, int NOUT>
__global__ void __launch_bounds__(256, 2) k_node_mma(
    const float* __restrict__ X, const __half* __restrict__ WT,
    const float* __restrict__ b1, __half* __restrict__ C, __half* __restrict__ D)
{
    extern __shared__ char smem[];
    const int tid = threadIdx.x;
    const int wid = tid >> 5, lid = tid & 31;
    const int warp_m = wid & 3, warp_n = wid >> 2;
    const int gid = lid >> 2, tig = lid & 3;

    const int m0 = blockIdx.x * 128;
    const int n0 = blockIdx.y * 128;

    const int fm = tid >> 1;
    const int fk = (tid & 1) * 32;
    const int gm = m0 + fm;
    const bool valid = gm < N_NODES;
    const float* rowX = X + (size_t)(valid ? gm : 0) * K + fk;
    const __half* rowW = WT + (size_t)(n0 + fm) * K + fk;

    float acc[2][8][4];
#pragma unroll
    for (int a = 0; a < 2; ++a)
#pragma unroll
        for (int b = 0; b < 8; ++b)
#pragma unroll
            for (int c = 0; c < 4; ++c) acc[a][b][c] = 0.f;

    constexpr int NCH = K / 64;
#pragma unroll 1
    for (int ch = 0; ch < NCH; ++ch) {
        // B tile
        {
            const uint4* wp = (const uint4*)(rowW + ch * 64);
            uint4 w0 = wp[0], w1 = wp[1], w2 = wp[2], w3 = wp[3];
            char* pb = smem + 18432 + fm * 144 + fk * 2;
            *(uint4*)pb        = w0;
            *(uint4*)(pb + 16) = w1;
            *(uint4*)(pb + 32) = w2;
            *(uint4*)(pb + 48) = w3;
        }
        // A tile: fp32 X -> fp16
        {
            char* pa = smem + fm * 144 + fk * 2;
#pragma unroll
            for (int q = 0; q < 4; ++q) {
                float4 x0 = make_float4(0.f, 0.f, 0.f, 0.f);
                float4 x1 = make_float4(0.f, 0.f, 0.f, 0.f);
                if (valid) {
                    x0 = *(const float4*)(rowX + ch * 64 + q * 8);
                    x1 = *(const float4*)(rowX + ch * 64 + q * 8 + 4);
                }
                __half2 h0 = __floats2half2_rn(x0.x, x0.y);
                __half2 h1 = __floats2half2_rn(x0.z, x0.w);
                __half2 h2 = __floats2half2_rn(x1.x, x1.y);
                __half2 h3 = __floats2half2_rn(x1.z, x1.w);
                *(uint4*)(pa + q * 16) = make_uint4(
                    *(uint32_t*)&h0, *(uint32_t*)&h1, *(uint32_t*)&h2, *(uint32_t*)&h3);
            }
        }
        __syncthreads();
#pragma unroll
        for (int ks = 0; ks < 4; ++ks) {
            const int koff = ks * 32 + tig * 4;
            uint32_t a[2][4];
#pragma unroll
            for (int mt = 0; mt < 2; ++mt) {
                int r = warp_m * 32 + mt * 16 + gid;
                const char* base = smem + r * 144;
                a[mt][0] = *(const uint32_t*)(base + koff);
                a[mt][1] = *(const uint32_t*)(base + 8 * 144 + koff);
                a[mt][2] = *(const uint32_t*)(base + koff + 16);
                a[mt][3] = *(const uint32_t*)(base + 8 * 144 + koff + 16);
            }
#pragma unroll
            for (int j = 0; j < 8; ++j) {
                int n = warp_n * 64 + j * 8 + gid;
                const char* bb = smem + 18432 + n * 144;
                uint32_t b0 = *(const uint32_t*)(bb + koff);
                uint32_t b1v = *(const uint32_t*)(bb + koff + 16);
                mma_f16(acc[0][j], a[0][0], a[0][1], a[0][2], a[0][3], b0, b1v);
                mma_f16(acc[1][j], a[1][0], a[1][1], a[1][2], a[1][3], b0, b1v);
            }
        }
        __syncthreads();
    }

    // epilogue: direct fp16 store to C (with bias) or D
    const bool isC = (n0 < NOUT);
    __half* OUT = isC ? C : D;
    const int cb = isC ? n0 : n0 - NOUT;
#pragma unroll
    for (int mt = 0; mt < 2; ++mt)
#pragma unroll
        for (int j = 0; j < 8; ++j) {
            int r = m0 + warp_m * 32 + mt * 16 + gid;
            int c = cb + warp_n * 64 + j * 8 + tig * 2;
            float bb0 = 0.f, bb1 = 0.f;
            if (isC) { bb0 = __ldg(b1 + c); bb1 = __ldg(b1 + c + 1); }
            if (r < N_NODES) {
                __half2 h = __floats2half2_rn(acc[mt][j][0] + bb0, acc[mt][j][1] + bb1);
                *(__half2*)&OUT[(size_t)r * NOUT + c] = h;
            }
            if (r + 8 < N_NODES) {
                __half2 h = __floats2half2_rn(acc[mt][j][2] + bb0, acc[mt][j][3] + bb1);
                *(__half2*)&OUT[(size_t)(r + 8) * NOUT + c] = h;
            }
        }
}

// ---------------- fp16 mma.sync edge GEMM + segmented max (full pipeline) ----------------
// A = relu(C16[dst]+D16[src]) from register-prefetched gathers;
// B = W2^T via cp.async double buffer. K chunk 64.
#define SM_SDST 0
#define SM_SSRC 512
#define SM_A    1024
#define SM_B0   19456
#define SM_B1   37888
#define SM_STG  1024
#define EDGE_SMEM 56320

template <int KW, int NOUT>
__global__ void __launch_bounds__(256, 2) k_edge_mma(
    const __half* __restrict__ C, const __half* __restrict__ D,
    const __half* __restrict__ WT, const float* __restrict__ b2, float* __restrict__ AGG)
{
    extern __shared__ char smem[];
    const uint32_t sb = smem_u32(smem);
    const int tid = threadIdx.x;
    const int wid = tid >> 5, lid = tid & 31;
    const int warp_m = wid & 3, warp_n = wid >> 2;
    const int gid = lid >> 2, tig = lid & 3;

    int* sdst = (int*)(smem + SM_SDST);
    int* ssrc = (int*)(smem + SM_SSRC);

    const int e0 = blockIdx.x * 128;
    const int n0 = blockIdx.y * 128;
    if (tid < 128) {
        sdst[tid] = g_dst_s[e0 + tid];
        ssrc[tid] = g_src_s[e0 + tid];
    }
    __syncthreads();

    const int fm = tid >> 1;
    const int fk = (tid & 1) * 32;
    const __half* rowC = C + (size_t)sdst[fm] * KW + fk;
    const __half* rowD = D + (size_t)ssrc[fm] * KW + fk;
    const __half* rowW = WT + (size_t)(n0 + fm) * KW + fk;
    const uint32_t bdst0 = sb + SM_B0 + fm * 144 + fk * 2;
    const uint32_t bdst1 = sb + SM_B1 + fm * 144 + fk * 2;

    float acc[2][8][4];
#pragma unroll
    for (int a = 0; a < 2; ++a)
#pragma unroll
        for (int b = 0; b < 8; ++b)
#pragma unroll
            for (int c = 0; c < 4; ++c) acc[a][b][c] = 0.f;

    constexpr int NCH = KW / 64;
    uint4 pc[4], pd[4];
    {   // prologue: prefetch chunk-0 gathers + async B(0)
        const uint4* cp = (const uint4*)rowC;
        const uint4* dp = (const uint4*)rowD;
#pragma unroll
        for (int q = 0; q < 4; ++q) { pc[q] = cp[q]; pd[q] = dp[q]; }
        cp16(bdst0,      rowW);
        cp16(bdst0 + 16, rowW + 8);
        cp16(bdst0 + 32, rowW + 16);
        cp16(bdst0 + 48, rowW + 24);
        cp_commit();
    }

#pragma unroll 1
    for (int ch = 0; ch < NCH; ++ch) {
        // ---- A tile: relu(C+D) from prefetched registers
        {
            uint4 ao[4];
#pragma unroll
            for (int q = 0; q < 4; ++q) {
                ao[q].x = haddrelu2(pc[q].x, pd[q].x);
                ao[q].y = haddrelu2(pc[q].y, pd[q].y);
                ao[q].z = haddrelu2(pc[q].z, pd[q].z);
                ao[q].w = haddrelu2(pc[q].w, pd[q].w);
            }
            char* pa = smem + SM_A + fm * 144 + fk * 2;
            *(uint4*)pa        = ao[0];
            *(uint4*)(pa + 16) = ao[1];
            *(uint4*)(pa + 32) = ao[2];
            *(uint4*)(pa + 48) = ao[3];
        }
        cp_wait_all();
        __syncthreads();

        // ---- prefetch next chunk: C/D -> regs, B -> other SMEM buffer (async)
        if (ch + 1 < NCH) {
            const uint4* cp = (const uint4*)(rowC + (ch + 1) * 64);
            const uint4* dp = (const uint4*)(rowD + (ch + 1) * 64);
#pragma unroll
            for (int q = 0; q < 4; ++q) { pc[q] = cp[q]; pd[q] = dp[q]; }
            const __half* ws = rowW + (ch + 1) * 64;
            uint32_t bd = ((ch + 1) & 1) ? bdst1 : bdst0;
            cp16(bd,      ws);
            cp16(bd + 16, ws + 8);
            cp16(bd + 32, ws + 16);
            cp16(bd + 48, ws + 24);
            cp_commit();
        }

        // ---- 4 k-steps of 16 from A + B[ch&1]
        const char* Bbuf = smem + ((ch & 1) ? SM_B1 : SM_B0);
#pragma unroll
        for (int ks = 0; ks < 4; ++ks) {
            const int koff = ks * 32 + tig * 4;
            uint32_t a[2][4];
#pragma unroll
            for (int mt = 0; mt < 2; ++mt) {
                int r = warp_m * 32 + mt * 16 + gid;
                const char* base = smem + SM_A + r * 144;
                a[mt][0] = *(const uint32_t*)(base + koff);
                a[mt][1] = *(const uint32_t*)(base + 8 * 144 + koff);
                a[mt][2] = *(const uint32_t*)(base + koff + 16);
                a[mt][3] = *(const uint32_t*)(base + 8 * 144 + koff + 16);
            }
#pragma unroll
            for (int j = 0; j < 8; ++j) {
                int n = warp_n * 64 + j * 8 + gid;
                const char* bb = Bbuf + n * 144;
                uint32_t b0 = *(const uint32_t*)(bb + koff);
                uint32_t b1 = *(const uint32_t*)(bb + koff + 16);
                mma_f16(acc[0][j], a[0][0], a[0][1], a[0][2], a[0][3], b0, b1);
                mma_f16(acc[1][j], a[1][0], a[1][1], a[1][2], a[1][3], b0, b1);
            }
        }
        __syncthreads();
    }

    // ---- epilogue: stage to SMEM, bias+relu, segmented max over sorted dst
    float* stage = (float*)(smem + SM_STG);
#pragma unroll 1
    for (int p = 0; p < 2; ++p) {
        if (warp_n == p) {
#pragma unroll
            for (int mt = 0; mt < 2; ++mt)
#pragma unroll
                for (int j = 0; j < 8; ++j) {
                    int r0 = warp_m * 32 + mt * 16 + gid;
                    int cw = j * 8 + tig * 2;
                    float* st = stage + r0 * 66 + cw;
                    st[0] = acc[mt][j][0];
                    st[1] = acc[mt][j][1];
                    st[66 * 8] = acc[mt][j][2];
                    st[66 * 8 + 1] = acc[mt][j][3];
                }
        }
        __syncthreads();
        {
            int colw = tid & 63;
            int grp = tid >> 6;
            int gcol = n0 + p * 64 + colw;
            float bias = b2[gcol];
            int prev = -1;
            float mx = 0.f;
#pragma unroll 4
            for (int r = grp * 32; r < grp * 32 + 32; ++r) {
                int d = sdst[r];
                float v = fmaxf(stage[r * 66 + colw] + bias, 0.f);
                if (d == prev) {
                    mx = fmaxf(mx, v);
                } else {
                    if (prev >= 0)
                        atomicMax((int*)&AGG[(size_t)prev * NOUT + gcol], __float_as_int(mx));
                    prev = d;
                    mx = v;
                }
            }
            atomicMax((int*)&AGG[(size_t)prev * NOUT + gcol], __float_as_int(mx));
        }
        __syncthreads();
    }
}

// ---------------- dense head ----------------
__global__ void k_head(const float* __restrict__ W3, const float* __restrict__ b3,
                       const float* __restrict__ W4, const float* __restrict__ b4,
                       float* __restrict__ out) {
    __shared__ float sh[128];
    __shared__ float red[2];
    int n = blockIdx.x;
    int t = threadIdx.x;   // 64 threads
    sh[t]      = g_H2[n * 128 + t];
    sh[t + 64] = g_H2[n * 128 + 64 + t];
    __syncthreads();
    float s = b3[t];
#pragma unroll 8
    for (int k = 0; k < 128; k++) s += sh[k] * W3[k * 64 + t];
    s = fmaxf(s, 0.f);
    float p = s * W4[t];
#pragma unroll
    for (int off = 16; off > 0; off >>= 1) p += __shfl_down_sync(0xffffffffu, p, off);
    if ((t & 31) == 0) red[t >> 5] = p;
    __syncthreads();
    if (t == 0) {
        float z = red[0] + red[1] + b4[0];
        out[n] = 1.f / (1.f + expf(-z));
    }
}

// ---------------- launch ----------------
extern "C" void kernel_launch(void* const* d_in, const int* in_sizes, int n_in,
                              void* d_out, int out_size) {
    const float* x   = (const float*)d_in[0];
    const int*   ei  = (const int*)d_in[1];
    const int*   src = ei;
    const int*   dst = ei + N_EDGES;
    const float* W1a = (const float*)d_in[2];
    const float* b1a = (const float*)d_in[3];
    const float* W2a = (const float*)d_in[4];
    const float* b2a = (const float*)d_in[5];
    const float* W1b = (const float*)d_in[6];
    const float* b1b = (const float*)d_in[7];
    const float* W2b = (const float*)d_in[8];
    const float* b2b = (const float*)d_in[9];
    const float* W3  = (const float*)d_in[10];
    const float* b3  = (const float*)d_in[11];
    const float* W4  = (const float*)d_in[12];
    const float* b4  = (const float*)d_in[13];
    float* out = (float*)d_out;

    void *pC1, *pD1, *pH1, *pC2, *pD2, *pH2, *pWT1, *pWT2, *pWTD1, *pWTD2;
    cudaGetSymbolAddress(&pC1, g_C1);
    cudaGetSymbolAddress(&pD1, g_D1);
    cudaGetSymbolAddress(&pH1, g_H1);
    cudaGetSymbolAddress(&pC2, g_C2);
    cudaGetSymbolAddress(&pD2, g_D2);
    cudaGetSymbolAddress(&pH2, g_H2);
    cudaGetSymbolAddress(&pWT1, g_WT1);
    cudaGetSymbolAddress(&pWT2, g_WT2);
    cudaGetSymbolAddress(&pWTD1, g_WTD1);
    cudaGetSymbolAddress(&pWTD2, g_WTD2);

    cudaFuncSetAttribute(k_edge_mma<512, 256>, cudaFuncAttributeMaxDynamicSharedMemorySize, EDGE_SMEM);
    cudaFuncSetAttribute(k_edge_mma<256, 128>, cudaFuncAttributeMaxDynamicSharedMemorySize, EDGE_SMEM);
    cudaFuncSetAttribute(k_node_mma<128, 512>, cudaFuncAttributeMaxDynamicSharedMemorySize, NODE_SMEM);
    cudaFuncSetAttribute(k_node_mma<256, 256>, cudaFuncAttributeMaxDynamicSharedMemorySize, NODE_SMEM);

    // init + counting sort
    k_zero<<<512, 256>>>();
    k_hist<<<(N_EDGES + 255) / 256, 256>>>(dst);
    k_scan<<<1, 1024>>>();
    k_scatter<<<(N_EDGES + 255) / 256, 256>>>(src, dst);

    // weight prep
    k_prep<512, 256><<<(512 * 256 + 255) / 256, 256>>>(W2a, (__half*)pWT1);
    k_prep<256, 128><<<(256 * 128 + 255) / 256, 256>>>(W2b, (__half*)pWT2);
    k_prep_dual<128, 512><<<(512 * 128 + 255) / 256, 256>>>(W1a, (__half*)pWTD1);
    k_prep_dual<256, 256><<<(256 * 256 + 255) / 256, 256>>>(W1b, (__half*)pWTD2);

    // layer 1
    {
        dim3 g((N_NODES + 127) / 128, 1024 / 128);
        k_node_mma<128, 512><<<g, 256, NODE_SMEM>>>(x, (const __half*)pWTD1, b1a,
                                                    (__half*)pC1, (__half*)pD1);
    }
    {
        dim3 g(N_EDGES / 128, 256 / 128);
        k_edge_mma<512, 256><<<g, 256, EDGE_SMEM>>>(
            (const __half*)pC1, (const __half*)pD1,
            (const __half*)pWT1, b2a, (float*)pH1);
    }

    // layer 2
    {
        dim3 g((N_NODES + 127) / 128, 512 / 128);
        k_node_mma<256, 256><<<g, 256, NODE_SMEM>>>((const float*)pH1, (const __half*)pWTD2, b1b,
                                                    (__half*)pC2, (__half*)pD2);
    }
    {
        dim3 g(N_EDGES / 128, 128 / 128);
        k_edge_mma<256, 128><<<g, 256, EDGE_SMEM>>>(
            (const __half*)pC2, (const __half*)pD2,
            (const __half*)pWT2, b2b, (float*)pH2);
    }

    // head
    k_head<<<N_NODES, 64>>>(W3, b3, W4, b4, out);
}